// round 8
// baseline (speedup 1.0000x reference)
#include <cuda_runtime.h>
#include <cuda_bf16.h>
#include <cstdint>
#include <cfloat>
#include <math.h>

#define BB 8
#define NN 1024
#define DD 2048
#define PP (3 * DD)   // packed projection width (K|Q|V)

// ---------------------------------------------------------------------------
// Scratch (allocation-free rule: static __device__ arrays)
// ---------------------------------------------------------------------------
static __device__ __align__(16) __nv_bfloat16 g_yh[BB * NN * DD], g_yl[BB * NN * DD];
static __device__ __align__(16) __nv_bfloat16 g_Wh[4 * DD * DD], g_Wl[4 * DD * DD]; // k,q,v,o stacked
static __device__ __align__(16) __nv_bfloat16 g_Ph[BB * NN * PP], g_Pl[BB * NN * PP]; // K|Q|V packed
static __device__ __align__(16) __nv_bfloat16 g_VTh[BB * NN * DD], g_VTl[BB * NN * DD];
static __device__ __align__(16) __nv_bfloat16 g_ATh[BB * NN * NN], g_ATl[BB * NN * NN];
static __device__ __align__(16) __nv_bfloat16 g_mh[BB * NN * DD], g_ml[BB * NN * DD];
static __device__ __align__(16) float         g_inv[BB * NN];

// ---------------------------------------------------------------------------
// Baseline-PTX helpers (sm_103 non-'a': mma.sync / ldmatrix / cp.async)
// ---------------------------------------------------------------------------
__device__ __forceinline__ uint32_t smem_u32(const void* p) {
    uint32_t a;
    asm("{ .reg .u64 t; cvta.to.shared.u64 t, %1; cvt.u32.u64 %0, t; }" : "=r"(a) : "l"(p));
    return a;
}
__device__ __forceinline__ void cp16(uint32_t dst, const void* src) {
    asm volatile("cp.async.cg.shared.global [%0], [%1], 16;" :: "r"(dst), "l"(src) : "memory");
}
#define CP_COMMIT() asm volatile("cp.async.commit_group;" ::: "memory")
#define CP_WAIT1()  asm volatile("cp.async.wait_group 1;" ::: "memory")

__device__ __forceinline__ void ldm_x4(uint32_t& r0, uint32_t& r1, uint32_t& r2, uint32_t& r3,
                                       uint32_t addr) {
    asm volatile("ldmatrix.sync.aligned.m8n8.x4.shared.b16 {%0,%1,%2,%3}, [%4];"
                 : "=r"(r0), "=r"(r1), "=r"(r2), "=r"(r3) : "r"(addr));
}
__device__ __forceinline__ void mma_bf16(float* c, const uint32_t* a, const uint32_t* b) {
    asm volatile(
        "mma.sync.aligned.m16n8k16.row.col.f32.bf16.bf16.f32 "
        "{%0,%1,%2,%3}, {%4,%5,%6,%7}, {%8,%9}, {%0,%1,%2,%3};"
        : "+f"(c[0]), "+f"(c[1]), "+f"(c[2]), "+f"(c[3])
        : "r"(a[0]), "r"(a[1]), "r"(a[2]), "r"(a[3]), "r"(b[0]), "r"(b[1]));
}

// ---------------------------------------------------------------------------
// HMMA GEMM:  C[M,Nc] = alpha * A[M,K] * B[Nc,K]^T   (bf16 hi/lo, fp32 acc)
// CTA tile 128x256x32, 256 threads (8 warps 2x4, warp tile 64x64), 1 CTA/SM.
// 3-stage cp.async pipeline, ONE __syncthreads per stage.
// SMEM: XOR-swizzled 64B rows; 48KB/stage (A 16K + B 32K).
// Warp tile 64x64 cuts smem LDSM traffic 1.5x vs 64x32 (smem-crossbar bound).
// mode 0: fp32 C.  mode 1: bf16 hi/lo split C.  mode 2: fp32 exp(C).
// ---------------------------------------------------------------------------
#define A_MATB 8192               // 128 rows x 64 B
#define B_MATB 16384              // 256 rows x 64 B
#define OFF_AH 0
#define OFF_AL 8192
#define OFF_BH 16384
#define OFF_BL 32768
#define STAGEB 49152
#define NSTG   3
#define SMEMB  (NSTG * STAGEB)    // 147456 B

__global__ __launch_bounds__(256, 1) void gemm_hmma(
    const __nv_bfloat16* __restrict__ Ah, const __nv_bfloat16* __restrict__ Al,
    const __nv_bfloat16* __restrict__ Bh, const __nv_bfloat16* __restrict__ Bl,
    float* __restrict__ Cf, __nv_bfloat16* __restrict__ Ch, __nv_bfloat16* __restrict__ Cl,
    int Nc, int K, int lda, int ldb, long sA, long sB, long sC, float alpha, int mode)
{
    extern __shared__ char smem[];
    const uint32_t sb = smem_u32(smem);

    const int tid  = threadIdx.x;
    const int wid  = tid >> 5;
    const int lane = tid & 31;
    const int m0 = blockIdx.y * 128, n0 = blockIdx.x * 256;

    const __nv_bfloat16* pA[2] = { Ah + (long)blockIdx.z * sA + (long)m0 * lda,
                                   Al + (long)blockIdx.z * sA + (long)m0 * lda };
    const __nv_bfloat16* pB[2] = { Bh + (long)blockIdx.z * sB + (long)n0 * ldb,
                                   Bl + (long)blockIdx.z * sB + (long)n0 * ldb };
    const long zC = (long)blockIdx.z * sC;

    // cp.async indices: A 128 rows x 4 chunks (2/thread/matrix),
    //                   B 256 rows x 4 chunks (4/thread/matrix)
    const int r0c = tid >> 2, q0 = tid & 3;
    const int r1c = r0c + 64;
    const int d0 = r0c * 64 + ((q0 ^ ((r0c >> 1) & 3)) * 16);
    const int d1 = r1c * 64 + ((q0 ^ ((r1c >> 1) & 3)) * 16);
    // B rows r0c + 64j share the same swizzle select ((r>>1)&3 invariant mod 64)

    const int wm0 = (wid >> 2) * 64;     // warp row offset (0/64)
    const int wn0 = (wid & 3) * 64;      // warp col offset (0/64/128/192)

    // ldmatrix lane addressing
    const int ra = wm0 + (lane & 15);                        // + 16*mi
    const int qa = (lane >> 4);                              // 0/1
    const int rb = wn0 + ((lane >> 3) & 2) * 4 + (lane & 7); // + 16*nb
    const int qb = ((lane >> 3) & 1);                        // 0/1
    const int sa  = (ra >> 1) & 3;   // invariant under +16*mi
    const int sbw = (rb >> 1) & 3;   // invariant under +16*nb

    float acc[4][8][4];
#pragma unroll
    for (int i = 0; i < 4; i++)
#pragma unroll
        for (int j = 0; j < 8; j++)
#pragma unroll
            for (int k = 0; k < 4; k++) acc[i][j][k] = 0.f;

    const int nst = K >> 5;

    // ---- prologue: issue stages 0 and 1 ----
#pragma unroll
    for (int pc = 0; pc < 2; pc++) {
        const int k0 = pc << 5;
        uint32_t s0 = sb + pc * STAGEB;
#pragma unroll
        for (int m = 0; m < 2; m++) {
            cp16(s0 + OFF_AH + m * A_MATB + d0, pA[m] + (long)r0c * lda + k0 + q0 * 8);
            cp16(s0 + OFF_AH + m * A_MATB + d1, pA[m] + (long)r1c * lda + k0 + q0 * 8);
#pragma unroll
            for (int j = 0; j < 4; j++)
                cp16(s0 + OFF_BH + m * B_MATB + d0 + j * 4096,
                     pB[m] + (long)(r0c + 64 * j) * ldb + k0 + q0 * 8);
        }
        CP_COMMIT();
    }

    int slot = 0, nslot = 2;
    for (int c = 0; c < nst; c++) {
        CP_WAIT1();          // stage c resident (c+1 may remain in flight)
        __syncthreads();

        if (c + 2 < nst) {
            const int k0 = (c + 2) << 5;
            uint32_t s1 = sb + nslot * STAGEB;
#pragma unroll
            for (int m = 0; m < 2; m++) {
                cp16(s1 + OFF_AH + m * A_MATB + d0, pA[m] + (long)r0c * lda + k0 + q0 * 8);
                cp16(s1 + OFF_AH + m * A_MATB + d1, pA[m] + (long)r1c * lda + k0 + q0 * 8);
#pragma unroll
                for (int j = 0; j < 4; j++)
                    cp16(s1 + OFF_BH + m * B_MATB + d0 + j * 4096,
                         pB[m] + (long)(r0c + 64 * j) * ldb + k0 + q0 * 8);
            }
        }
        CP_COMMIT();
        if (++nslot == NSTG) nslot = 0;

        const uint32_t st = sb + slot * STAGEB;
        if (++slot == NSTG) slot = 0;

#pragma unroll
        for (int s = 0; s < 2; s++) {    // two k16 slabs
            const int qla = (s * 2 + qa) ^ sa;
            const int qlb = (s * 2 + qb) ^ sbw;
            const uint32_t aHb = st + OFF_AH + ra * 64 + qla * 16;
            const uint32_t aLb = st + OFF_AL + ra * 64 + qla * 16;
            const uint32_t bHb = st + OFF_BH + rb * 64 + qlb * 16;
            const uint32_t bLb = st + OFF_BL + rb * 64 + qlb * 16;

            // B fragments for this slab: 4 n16 blocks, hi+lo
            uint32_t bh[4][4], bl[4][4];
#pragma unroll
            for (int nb = 0; nb < 4; nb++) {
                ldm_x4(bh[nb][0], bh[nb][1], bh[nb][2], bh[nb][3], bHb + nb * 1024);
                ldm_x4(bl[nb][0], bl[nb][1], bl[nb][2], bl[nb][3], bLb + nb * 1024);
            }
#pragma unroll
            for (int mi = 0; mi < 4; mi++) {
                uint32_t ah[4], al[4];
                ldm_x4(ah[0], ah[1], ah[2], ah[3], aHb + mi * 1024);
                ldm_x4(al[0], al[1], al[2], al[3], aLb + mi * 1024);
#pragma unroll
                for (int ni = 0; ni < 8; ni++) {
                    const uint32_t* bhf = &bh[ni >> 1][(ni & 1) * 2];
                    const uint32_t* blf = &bl[ni >> 1][(ni & 1) * 2];
                    mma_bf16(acc[mi][ni], ah, bhf);
                    mma_bf16(acc[mi][ni], ah, blf);
                    mma_bf16(acc[mi][ni], al, bhf);
                }
            }
        }
    }

    // ---- epilogue ----
    const int er = lane >> 2;
    const int ec = (lane & 3) * 2;
#pragma unroll
    for (int mi = 0; mi < 4; mi++) {
#pragma unroll
        for (int ni = 0; ni < 8; ni++) {
            const int row = m0 + wm0 + 16 * mi + er;
            const int col = n0 + wn0 + 8 * ni + ec;
            float v0 = acc[mi][ni][0] * alpha, v1 = acc[mi][ni][1] * alpha;
            float v2 = acc[mi][ni][2] * alpha, v3 = acc[mi][ni][3] * alpha;
            if (mode == 0) {
                *reinterpret_cast<float2*>(Cf + zC + (long)row * Nc + col) = make_float2(v0, v1);
                *reinterpret_cast<float2*>(Cf + zC + (long)(row + 8) * Nc + col) = make_float2(v2, v3);
            } else if (mode == 2) {
                *reinterpret_cast<float2*>(Cf + zC + (long)row * Nc + col) =
                    make_float2(__expf(v0), __expf(v1));
                *reinterpret_cast<float2*>(Cf + zC + (long)(row + 8) * Nc + col) =
                    make_float2(__expf(v2), __expf(v3));
            } else {
                __nv_bfloat162 h, l;
                h.x = __float2bfloat16(v0); l.x = __float2bfloat16(v0 - __bfloat162float(h.x));
                h.y = __float2bfloat16(v1); l.y = __float2bfloat16(v1 - __bfloat162float(h.y));
                *reinterpret_cast<__nv_bfloat162*>(Ch + zC + (long)row * Nc + col) = h;
                *reinterpret_cast<__nv_bfloat162*>(Cl + zC + (long)row * Nc + col) = l;
                h.x = __float2bfloat16(v2); l.x = __float2bfloat16(v2 - __bfloat162float(h.x));
                h.y = __float2bfloat16(v3); l.y = __float2bfloat16(v3 - __bfloat162float(h.y));
                *reinterpret_cast<__nv_bfloat162*>(Ch + zC + (long)(row + 8) * Nc + col) = h;
                *reinterpret_cast<__nv_bfloat162*>(Cl + zC + (long)(row + 8) * Nc + col) = l;
            }
        }
    }
}

// ---------------------------------------------------------------------------
// fp32 -> bf16 hi/lo elementwise split (y)
// ---------------------------------------------------------------------------
__global__ __launch_bounds__(256) void splitf_k(const float* __restrict__ x,
    __nv_bfloat16* __restrict__ hi, __nv_bfloat16* __restrict__ lo, long n)
{
    long i = ((long)blockIdx.x * 256 + threadIdx.x) * 4;
    if (i >= n) return;
    float4 v = *reinterpret_cast<const float4*>(x + i);
    __nv_bfloat162 h01, h23, l01, l23;
    h01.x = __float2bfloat16(v.x); l01.x = __float2bfloat16(v.x - __bfloat162float(h01.x));
    h01.y = __float2bfloat16(v.y); l01.y = __float2bfloat16(v.y - __bfloat162float(h01.y));
    h23.x = __float2bfloat16(v.z); l23.x = __float2bfloat16(v.z - __bfloat162float(h23.x));
    h23.y = __float2bfloat16(v.w); l23.y = __float2bfloat16(v.w - __bfloat162float(h23.y));
    uint2 hv, lv;
    hv.x = *reinterpret_cast<uint32_t*>(&h01); hv.y = *reinterpret_cast<uint32_t*>(&h23);
    lv.x = *reinterpret_cast<uint32_t*>(&l01); lv.y = *reinterpret_cast<uint32_t*>(&l23);
    *reinterpret_cast<uint2*>(hi + i) = hv;
    *reinterpret_cast<uint2*>(lo + i) = lv;
}

// ---------------------------------------------------------------------------
// 4 weight matrices split in one launch (z selects source; Wq scaled by 0.1)
// ---------------------------------------------------------------------------
__global__ __launch_bounds__(256) void splitW_k(
    const float* __restrict__ w0, const float* __restrict__ w1,
    const float* __restrict__ w2, const float* __restrict__ w3,
    __nv_bfloat16* __restrict__ hi, __nv_bfloat16* __restrict__ lo)
{
    const int z = blockIdx.z;
    const float* src = (z == 0) ? w0 : (z == 1) ? w1 : (z == 2) ? w2 : w3;
    const float scale = (z == 1) ? 0.1f : 1.0f;
    const long dd = (long)DD * DD;
    long i = ((long)blockIdx.x * 256 + threadIdx.x) * 4;
    if (i >= dd) return;
    float4 v = *reinterpret_cast<const float4*>(src + i);
    v.x *= scale; v.y *= scale; v.z *= scale; v.w *= scale;
    __nv_bfloat162 h01, h23, l01, l23;
    h01.x = __float2bfloat16(v.x); l01.x = __float2bfloat16(v.x - __bfloat162float(h01.x));
    h01.y = __float2bfloat16(v.y); l01.y = __float2bfloat16(v.y - __bfloat162float(h01.y));
    h23.x = __float2bfloat16(v.z); l23.x = __float2bfloat16(v.z - __bfloat162float(h23.x));
    h23.y = __float2bfloat16(v.w); l23.y = __float2bfloat16(v.w - __bfloat162float(h23.y));
    long o = z * dd + i;
    uint2 hv, lv;
    hv.x = *reinterpret_cast<uint32_t*>(&h01); hv.y = *reinterpret_cast<uint32_t*>(&h23);
    lv.x = *reinterpret_cast<uint32_t*>(&l01); lv.y = *reinterpret_cast<uint32_t*>(&l23);
    *reinterpret_cast<uint2*>(hi + o) = hv;
    *reinterpret_cast<uint2*>(lo + o) = lv;
}

// ---------------------------------------------------------------------------
// Column sums of exp-logits (diag excluded) -> inv[b][j] = 1/sum
// ---------------------------------------------------------------------------
__global__ __launch_bounds__(256) void colsum_k(const float* __restrict__ Aw,
                                                float* __restrict__ inv)
{
    const int j = blockIdx.x * blockDim.x + threadIdx.x;
    const float* Mb = Aw + (long)blockIdx.y * NN * NN;
    float s0 = 0.f, s1 = 0.f, s2 = 0.f, s3 = 0.f;
#pragma unroll 4
    for (int i = 0; i < NN; i += 4) {
        s0 += Mb[(long)(i + 0) * NN + j];
        s1 += Mb[(long)(i + 1) * NN + j];
        s2 += Mb[(long)(i + 2) * NN + j];
        s3 += Mb[(long)(i + 3) * NN + j];
    }
    float s = (s0 + s1) + (s2 + s3);
    s -= Mb[(long)j * NN + j];   // exclude diagonal junk term
    inv[blockIdx.y * NN + j] = 1.f / s;
}

// ---------------------------------------------------------------------------
// Fused: normalize exp-Aw (write back fp32, diag=0) + transpose + bf16 split.
// AT[j][i] = Aw[i][j] * inv[j]  (diag 0)
// ---------------------------------------------------------------------------
__global__ __launch_bounds__(256) void normtsplit_k(float* __restrict__ Aw,
    const float* __restrict__ inv,
    __nv_bfloat16* __restrict__ oh, __nv_bfloat16* __restrict__ ol)
{
    __shared__ float t[32][33];
    const long nn = (long)NN * NN;
    float* Mb = Aw + (long)blockIdx.z * nn;
    const float* ib = inv + (long)blockIdx.z * NN;
    int r0 = blockIdx.y * 32, c0 = blockIdx.x * 32;
    int tx = threadIdx.x, ty = threadIdx.y;
    const float sc = ib[c0 + tx];           // normalization for column c0+tx
#pragma unroll
    for (int i = 0; i < 4; i++) {
        int r = r0 + ty + i * 8;
        long o = (long)r * NN + c0 + tx;
        float v = Mb[o] * sc;
        if (r == c0 + tx) v = 0.f;
        Mb[o] = v;                          // write back normalized weights
        t[ty + i * 8][tx] = v;
    }
    __syncthreads();
    long ob = (long)blockIdx.z * nn;
#pragma unroll
    for (int i = 0; i < 4; i++) {
        float v = t[tx][ty + i * 8];
        __nv_bfloat16 h = __float2bfloat16(v);
        __nv_bfloat16 l = __float2bfloat16(v - __bfloat162float(h));
        long o = ob + (long)(c0 + ty + i * 8) * NN + r0 + tx;
        oh[o] = h; ol[o] = l;
    }
}

// ---------------------------------------------------------------------------
// bf16 transpose (hi & lo in one pass): out[c][r] = in[r][c]
// ---------------------------------------------------------------------------
__global__ __launch_bounds__(256) void tbf16_k(
    const __nv_bfloat16* __restrict__ ih, const __nv_bfloat16* __restrict__ il,
    __nv_bfloat16* __restrict__ oh, __nv_bfloat16* __restrict__ ol,
    int R, int C, int ldin, long sIn, long sOut)
{
    __shared__ __nv_bfloat16 th[32][33], tl[32][33];
    long ibo = (long)blockIdx.z * sIn;
    int r0 = blockIdx.y * 32, c0 = blockIdx.x * 32;
    int tx = threadIdx.x, ty = threadIdx.y;
#pragma unroll
    for (int i = 0; i < 4; i++) {
        long o = ibo + (long)(r0 + ty + i * 8) * ldin + c0 + tx;
        th[ty + i * 8][tx] = ih[o];
        tl[ty + i * 8][tx] = il[o];
    }
    __syncthreads();
    long ob = (long)blockIdx.z * sOut;
#pragma unroll
    for (int i = 0; i < 4; i++) {
        long o = ob + (long)(c0 + ty + i * 8) * R + r0 + tx;
        oh[o] = th[tx][ty + i * 8];
        ol[o] = tl[tx][ty + i * 8];
    }
}

// ---------------------------------------------------------------------------
extern "C" void kernel_launch(void* const* d_in, const int* in_sizes, int n_in,
                              void* d_out, int out_size)
{
    const float* y  = (const float*)d_in[0];
    const float* Wk = (const float*)d_in[1];
    const float* Wq = (const float*)d_in[2];
    const float* Wv = (const float*)d_in[3];
    const float* Wo = (const float*)d_in[4];

    float* out = (float*)d_out;
    float* Aw  = out + (long)BB * NN * DD;

    __nv_bfloat16 *yh, *yl, *Wh, *Wl, *Ph, *Pl, *VTh, *VTl, *ATh, *ATl, *mh, *ml;
    float* inv;
    cudaGetSymbolAddress((void**)&yh, g_yh);   cudaGetSymbolAddress((void**)&yl, g_yl);
    cudaGetSymbolAddress((void**)&Wh, g_Wh);   cudaGetSymbolAddress((void**)&Wl, g_Wl);
    cudaGetSymbolAddress((void**)&Ph, g_Ph);   cudaGetSymbolAddress((void**)&Pl, g_Pl);
    cudaGetSymbolAddress((void**)&VTh, g_VTh); cudaGetSymbolAddress((void**)&VTl, g_VTl);
    cudaGetSymbolAddress((void**)&ATh, g_ATh); cudaGetSymbolAddress((void**)&ATl, g_ATl);
    cudaGetSymbolAddress((void**)&mh, g_mh);   cudaGetSymbolAddress((void**)&ml, g_ml);
    cudaGetSymbolAddress((void**)&inv, g_inv);

    cudaFuncSetAttribute(gemm_hmma, cudaFuncAttributeMaxDynamicSharedMemorySize, SMEMB);

    const long nd = (long)NN * DD;
    const long np = (long)NN * PP;
    const long nn = (long)NN * NN;
    const long dd = (long)DD * DD;
    const long nY = (long)BB * NN * DD;

    // 1) splits: W stacked [Wk; 0.1*Wq; Wv; Wo] (one launch), then y
    {
        dim3 gw((unsigned)(dd / 1024), 1, 4);
        splitW_k<<<gw, 256>>>(Wk, Wq, Wv, Wo, Wh, Wl);
        splitf_k<<<(int)(nY / 1024), 256>>>(y, yh, yl, nY);
    }

    // 2) fused projection: P[8192, 6144] = y @ [Wk;0.1Wq;Wv]^T -> bf16 split
    {
        dim3 g(PP / 256, (BB * NN) / 128, 1);
        gemm_hmma<<<g, 256, SMEMB>>>(yh, yl, Wh, Wl, nullptr, Ph, Pl,
                                     PP, DD, DD, DD, 0, 0, 0, 1.0f, 1);
    }

    // 3) logits per batch with fused exp: Aw[b] = exp(Q_b @ K_b^T) (fp32)
    {
        dim3 g(NN / 256, NN / 128, BB);
        gemm_hmma<<<g, 256, SMEMB>>>(Ph + DD, Pl + DD, Ph, Pl, Aw, nullptr, nullptr,
                                     NN, DD, PP, PP, np, np, nn, 1.0f, 2);
    }

    // 4) V transpose (bf16 hi/lo direct)
    {
        dim3 g2(DD / 32, NN / 32, BB);
        tbf16_k<<<g2, dim3(32, 8)>>>(Ph + 2 * DD, Pl + 2 * DD, VTh, VTl,
                                     NN, DD, PP, np, nd);
    }

    // 5) column sums (diag excluded) -> inv
    {
        dim3 g(NN / 256, BB, 1);
        colsum_k<<<g, 256>>>(Aw, inv);
    }

    // 6) fused normalize (writeback, diag=0) + transpose + bf16 split -> AT
    {
        dim3 g(NN / 32, NN / 32, BB);
        normtsplit_k<<<g, dim3(32, 8)>>>(Aw, inv, ATh, ATl);
    }

    // 7) mid[b] = AT_b @ VT_b^T -> bf16 split
    {
        dim3 g(DD / 256, NN / 128, BB);
        gemm_hmma<<<g, 256, SMEMB>>>(ATh, ATl, VTh, VTl, nullptr, mh, ml,
                                     DD, NN, NN, NN, nn, nd, nd, 1.0f, 1);
    }

    // 8) out = mid @ Wo^T (flat) -> fp32 d_out
    {
        dim3 g(DD / 256, (BB * NN) / 128, 1);
        gemm_hmma<<<g, 256, SMEMB>>>(mh, ml, Wh + 3 * dd, Wl + 3 * dd, out, nullptr, nullptr,
                                     DD, DD, DD, DD, 0, 0, 0, 1.0f, 0);
    }
}

// round 9
// speedup vs baseline: 1.2782x; 1.2782x over previous
#include <cuda_runtime.h>
#include <cuda_bf16.h>
#include <cstdint>
#include <cfloat>
#include <math.h>

#define BB 8
#define NN 1024
#define DD 2048
#define PP (3 * DD)   // packed projection width (K|Q|VW)

// ---------------------------------------------------------------------------
// Scratch (allocation-free rule: static __device__ arrays)
// W slots: 0=Wk, 1=0.1*Wq, 2=W3(=Wo@Wv), 3=Wo, 4=Wv^T
// ---------------------------------------------------------------------------
static __device__ __align__(16) __nv_bfloat16 g_yh[BB * NN * DD], g_yl[BB * NN * DD];
static __device__ __align__(16) __nv_bfloat16 g_Wh[5 * DD * DD], g_Wl[5 * DD * DD];
static __device__ __align__(16) __nv_bfloat16 g_Ph[BB * NN * PP], g_Pl[BB * NN * PP]; // K|Q|VW packed
static __device__ __align__(16) __nv_bfloat16 g_VTh[BB * NN * DD], g_VTl[BB * NN * DD];
static __device__ __align__(16) __nv_bfloat16 g_ATh[BB * NN * NN], g_ATl[BB * NN * NN];
static __device__ __align__(16) float         g_inv[BB * NN];

// ---------------------------------------------------------------------------
// Baseline-PTX helpers (sm_103 non-'a': mma.sync / ldmatrix / cp.async)
// ---------------------------------------------------------------------------
__device__ __forceinline__ uint32_t smem_u32(const void* p) {
    uint32_t a;
    asm("{ .reg .u64 t; cvta.to.shared.u64 t, %1; cvt.u32.u64 %0, t; }" : "=r"(a) : "l"(p));
    return a;
}
__device__ __forceinline__ void cp16(uint32_t dst, const void* src) {
    asm volatile("cp.async.cg.shared.global [%0], [%1], 16;" :: "r"(dst), "l"(src) : "memory");
}
#define CP_COMMIT() asm volatile("cp.async.commit_group;" ::: "memory")
#define CP_WAIT1()  asm volatile("cp.async.wait_group 1;" ::: "memory")

__device__ __forceinline__ void ldm_x4(uint32_t& r0, uint32_t& r1, uint32_t& r2, uint32_t& r3,
                                       uint32_t addr) {
    asm volatile("ldmatrix.sync.aligned.m8n8.x4.shared.b16 {%0,%1,%2,%3}, [%4];"
                 : "=r"(r0), "=r"(r1), "=r"(r2), "=r"(r3) : "r"(addr));
}
__device__ __forceinline__ void mma_bf16(float* c, const uint32_t* a, const uint32_t* b) {
    asm volatile(
        "mma.sync.aligned.m16n8k16.row.col.f32.bf16.bf16.f32 "
        "{%0,%1,%2,%3}, {%4,%5,%6,%7}, {%8,%9}, {%0,%1,%2,%3};"
        : "+f"(c[0]), "+f"(c[1]), "+f"(c[2]), "+f"(c[3])
        : "r"(a[0]), "r"(a[1]), "r"(a[2]), "r"(a[3]), "r"(b[0]), "r"(b[1]));
}

// ---------------------------------------------------------------------------
// HMMA GEMM (R6 measured-best core):  C = alpha * A[M,K] * B[Nc,K]^T
// tile 128x128x32, 256 threads (8 warps, 64x32), 3-stage cp.async,
// ONE __syncthreads per stage, XOR-swizzled 64B rows, 2 CTAs/SM.
// mode 0: fp32 C.  mode 1: bf16 hi/lo split C.  mode 2: fp32 exp(C).
// ---------------------------------------------------------------------------
#define MATB   8192               // 128 rows x 64 B
#define STAGEB (4 * MATB)         // Ah, Al, Bh, Bl = 32768 B
#define NSTG   3
#define SMEMB  (NSTG * STAGEB)    // 98304 B

__global__ __launch_bounds__(256, 2) void gemm_hmma(
    const __nv_bfloat16* __restrict__ Ah, const __nv_bfloat16* __restrict__ Al,
    const __nv_bfloat16* __restrict__ Bh, const __nv_bfloat16* __restrict__ Bl,
    float* __restrict__ Cf, __nv_bfloat16* __restrict__ Ch, __nv_bfloat16* __restrict__ Cl,
    int Nc, int K, int lda, int ldb, long sA, long sB, long sC, float alpha, int mode)
{
    extern __shared__ char smem[];
    const uint32_t sb = smem_u32(smem);

    const int tid  = threadIdx.x;
    const int wid  = tid >> 5;
    const int lane = tid & 31;
    const int m0 = blockIdx.y * 128, n0 = blockIdx.x * 128;

    const __nv_bfloat16* pA[2] = { Ah + (long)blockIdx.z * sA + (long)m0 * lda,
                                   Al + (long)blockIdx.z * sA + (long)m0 * lda };
    const __nv_bfloat16* pB[2] = { Bh + (long)blockIdx.z * sB + (long)n0 * ldb,
                                   Bl + (long)blockIdx.z * sB + (long)n0 * ldb };
    const long zC = (long)blockIdx.z * sC;

    const int r0c = tid >> 2, q0 = tid & 3;
    const int r1c = r0c + 64, q1 = q0;
    const int d0 = r0c * 64 + ((q0 ^ ((r0c >> 1) & 3)) * 16);
    const int d1 = r1c * 64 + ((q1 ^ ((r1c >> 1) & 3)) * 16);

    const int wm0 = (wid >> 2) * 64;
    const int wn0 = (wid & 3) * 32;

    const int ra = wm0 + (lane & 15);
    const int qa = (lane >> 4);
    const int rb = wn0 + ((lane >> 3) & 2) * 4 + (lane & 7);
    const int qb = ((lane >> 3) & 1);
    const int sa  = (ra >> 1) & 3;
    const int sbw = (rb >> 1) & 3;

    float acc[4][4][4];
#pragma unroll
    for (int i = 0; i < 4; i++)
#pragma unroll
        for (int j = 0; j < 4; j++)
#pragma unroll
            for (int k = 0; k < 4; k++) acc[i][j][k] = 0.f;

    const int nst = K >> 5;

#pragma unroll
    for (int pc = 0; pc < 2; pc++) {
        const int k0 = pc << 5;
        uint32_t s0 = sb + pc * STAGEB;
#pragma unroll
        for (int m = 0; m < 2; m++) {
            cp16(s0 + m * MATB + d0, pA[m] + (long)r0c * lda + k0 + q0 * 8);
            cp16(s0 + m * MATB + d1, pA[m] + (long)r1c * lda + k0 + q1 * 8);
            cp16(s0 + (2 + m) * MATB + d0, pB[m] + (long)r0c * ldb + k0 + q0 * 8);
            cp16(s0 + (2 + m) * MATB + d1, pB[m] + (long)r1c * ldb + k0 + q1 * 8);
        }
        CP_COMMIT();
    }

    int slot = 0, nslot = 2;
    for (int c = 0; c < nst; c++) {
        CP_WAIT1();
        __syncthreads();

        if (c + 2 < nst) {
            const int k0 = (c + 2) << 5;
            uint32_t s1 = sb + nslot * STAGEB;
#pragma unroll
            for (int m = 0; m < 2; m++) {
                cp16(s1 + m * MATB + d0, pA[m] + (long)r0c * lda + k0 + q0 * 8);
                cp16(s1 + m * MATB + d1, pA[m] + (long)r1c * lda + k0 + q1 * 8);
                cp16(s1 + (2 + m) * MATB + d0, pB[m] + (long)r0c * ldb + k0 + q0 * 8);
                cp16(s1 + (2 + m) * MATB + d1, pB[m] + (long)r1c * ldb + k0 + q1 * 8);
            }
        }
        CP_COMMIT();
        if (++nslot == NSTG) nslot = 0;

        const uint32_t st = sb + slot * STAGEB;
        if (++slot == NSTG) slot = 0;

#pragma unroll
        for (int s = 0; s < 2; s++) {
            const int qla = (s * 2 + qa) ^ sa;
            const int qlb = (s * 2 + qb) ^ sbw;
            const uint32_t aHb = st + 0 * MATB + ra * 64 + qla * 16;
            const uint32_t aLb = st + 1 * MATB + ra * 64 + qla * 16;
            const uint32_t bHb = st + 2 * MATB + rb * 64 + qlb * 16;
            const uint32_t bLb = st + 3 * MATB + rb * 64 + qlb * 16;

            uint32_t bh[2][4], bl[2][4];
#pragma unroll
            for (int nb = 0; nb < 2; nb++) {
                ldm_x4(bh[nb][0], bh[nb][1], bh[nb][2], bh[nb][3], bHb + nb * 1024);
                ldm_x4(bl[nb][0], bl[nb][1], bl[nb][2], bl[nb][3], bLb + nb * 1024);
            }
#pragma unroll
            for (int mi = 0; mi < 4; mi++) {
                uint32_t ah[4], al[4];
                ldm_x4(ah[0], ah[1], ah[2], ah[3], aHb + mi * 1024);
                ldm_x4(al[0], al[1], al[2], al[3], aLb + mi * 1024);
#pragma unroll
                for (int ni = 0; ni < 4; ni++) {
                    const uint32_t* bhf = &bh[ni >> 1][(ni & 1) * 2];
                    const uint32_t* blf = &bl[ni >> 1][(ni & 1) * 2];
                    mma_bf16(acc[mi][ni], ah, bhf);
                    mma_bf16(acc[mi][ni], ah, blf);
                    mma_bf16(acc[mi][ni], al, bhf);
                }
            }
        }
    }

    const int er = lane >> 2;
    const int ec = (lane & 3) * 2;
#pragma unroll
    for (int mi = 0; mi < 4; mi++) {
#pragma unroll
        for (int ni = 0; ni < 4; ni++) {
            const int row = m0 + wm0 + 16 * mi + er;
            const int col = n0 + wn0 + 8 * ni + ec;
            float v0 = acc[mi][ni][0] * alpha, v1 = acc[mi][ni][1] * alpha;
            float v2 = acc[mi][ni][2] * alpha, v3 = acc[mi][ni][3] * alpha;
            if (mode == 0) {
                *reinterpret_cast<float2*>(Cf + zC + (long)row * Nc + col) = make_float2(v0, v1);
                *reinterpret_cast<float2*>(Cf + zC + (long)(row + 8) * Nc + col) = make_float2(v2, v3);
            } else if (mode == 2) {
                *reinterpret_cast<float2*>(Cf + zC + (long)row * Nc + col) =
                    make_float2(__expf(v0), __expf(v1));
                *reinterpret_cast<float2*>(Cf + zC + (long)(row + 8) * Nc + col) =
                    make_float2(__expf(v2), __expf(v3));
            } else {
                __nv_bfloat162 h, l;
                h.x = __float2bfloat16(v0); l.x = __float2bfloat16(v0 - __bfloat162float(h.x));
                h.y = __float2bfloat16(v1); l.y = __float2bfloat16(v1 - __bfloat162float(h.y));
                *reinterpret_cast<__nv_bfloat162*>(Ch + zC + (long)row * Nc + col) = h;
                *reinterpret_cast<__nv_bfloat162*>(Cl + zC + (long)row * Nc + col) = l;
                h.x = __float2bfloat16(v2); l.x = __float2bfloat16(v2 - __bfloat162float(h.x));
                h.y = __float2bfloat16(v3); l.y = __float2bfloat16(v3 - __bfloat162float(h.y));
                *reinterpret_cast<__nv_bfloat162*>(Ch + zC + (long)(row + 8) * Nc + col) = h;
                *reinterpret_cast<__nv_bfloat162*>(Cl + zC + (long)(row + 8) * Nc + col) = l;
            }
        }
    }
}

// ---------------------------------------------------------------------------
// fp32 -> bf16 hi/lo elementwise split (y)
// ---------------------------------------------------------------------------
__global__ __launch_bounds__(256) void splitf_k(const float* __restrict__ x,
    __nv_bfloat16* __restrict__ hi, __nv_bfloat16* __restrict__ lo, long n)
{
    long i = ((long)blockIdx.x * 256 + threadIdx.x) * 4;
    if (i >= n) return;
    float4 v = *reinterpret_cast<const float4*>(x + i);
    __nv_bfloat162 h01, h23, l01, l23;
    h01.x = __float2bfloat16(v.x); l01.x = __float2bfloat16(v.x - __bfloat162float(h01.x));
    h01.y = __float2bfloat16(v.y); l01.y = __float2bfloat16(v.y - __bfloat162float(h01.y));
    h23.x = __float2bfloat16(v.z); l23.x = __float2bfloat16(v.z - __bfloat162float(h23.x));
    h23.y = __float2bfloat16(v.w); l23.y = __float2bfloat16(v.w - __bfloat162float(h23.y));
    uint2 hv, lv;
    hv.x = *reinterpret_cast<uint32_t*>(&h01); hv.y = *reinterpret_cast<uint32_t*>(&h23);
    lv.x = *reinterpret_cast<uint32_t*>(&l01); lv.y = *reinterpret_cast<uint32_t*>(&l23);
    *reinterpret_cast<uint2*>(hi + i) = hv;
    *reinterpret_cast<uint2*>(lo + i) = lv;
}

// ---------------------------------------------------------------------------
// W splits: z=0 -> Wk (slot 0), z=1 -> 0.1*Wq (slot 1), z=2 -> Wo (slot 3)
// ---------------------------------------------------------------------------
__global__ __launch_bounds__(256) void splitW_k(
    const float* __restrict__ w0, const float* __restrict__ w1,
    const float* __restrict__ w2,
    __nv_bfloat16* __restrict__ hi, __nv_bfloat16* __restrict__ lo)
{
    const int z = blockIdx.z;
    const float* src = (z == 0) ? w0 : (z == 1) ? w1 : w2;
    const float scale = (z == 1) ? 0.1f : 1.0f;
    const int slot = (z == 2) ? 3 : z;
    const long dd = (long)DD * DD;
    long i = ((long)blockIdx.x * 256 + threadIdx.x) * 4;
    if (i >= dd) return;
    float4 v = *reinterpret_cast<const float4*>(src + i);
    v.x *= scale; v.y *= scale; v.z *= scale; v.w *= scale;
    __nv_bfloat162 h01, h23, l01, l23;
    h01.x = __float2bfloat16(v.x); l01.x = __float2bfloat16(v.x - __bfloat162float(h01.x));
    h01.y = __float2bfloat16(v.y); l01.y = __float2bfloat16(v.y - __bfloat162float(h01.y));
    h23.x = __float2bfloat16(v.z); l23.x = __float2bfloat16(v.z - __bfloat162float(h23.x));
    h23.y = __float2bfloat16(v.w); l23.y = __float2bfloat16(v.w - __bfloat162float(h23.y));
    long o = (long)slot * dd + i;
    uint2 hv, lv;
    hv.x = *reinterpret_cast<uint32_t*>(&h01); hv.y = *reinterpret_cast<uint32_t*>(&h23);
    lv.x = *reinterpret_cast<uint32_t*>(&l01); lv.y = *reinterpret_cast<uint32_t*>(&l23);
    *reinterpret_cast<uint2*>(hi + o) = hv;
    *reinterpret_cast<uint2*>(lo + o) = lv;
}

// ---------------------------------------------------------------------------
// transpose + split fp32 -> bf16 hi/lo: out[c][r] = split(in[r][c])
// ---------------------------------------------------------------------------
__global__ __launch_bounds__(256) void tsplit_k(const float* __restrict__ in,
    __nv_bfloat16* __restrict__ oh, __nv_bfloat16* __restrict__ ol,
    int R, int C)
{
    __shared__ float t[32][33];
    int r0 = blockIdx.y * 32, c0 = blockIdx.x * 32;
    int tx = threadIdx.x, ty = threadIdx.y;
#pragma unroll
    for (int i = 0; i < 4; i++)
        t[ty + i * 8][tx] = in[(long)(r0 + ty + i * 8) * C + c0 + tx];
    __syncthreads();
#pragma unroll
    for (int i = 0; i < 4; i++) {
        float v = t[tx][ty + i * 8];
        __nv_bfloat16 h = __float2bfloat16(v);
        __nv_bfloat16 l = __float2bfloat16(v - __bfloat162float(h));
        long o = (long)(c0 + ty + i * 8) * R + r0 + tx;
        oh[o] = h; ol[o] = l;
    }
}

// ---------------------------------------------------------------------------
// Column sums of exp-logits (diag excluded) -> inv[b][j] = 1/sum
// ---------------------------------------------------------------------------
__global__ __launch_bounds__(256) void colsum_k(const float* __restrict__ Aw,
                                                float* __restrict__ inv)
{
    const int j = blockIdx.x * blockDim.x + threadIdx.x;
    const float* Mb = Aw + (long)blockIdx.y * NN * NN;
    float s0 = 0.f, s1 = 0.f, s2 = 0.f, s3 = 0.f;
#pragma unroll 4
    for (int i = 0; i < NN; i += 4) {
        s0 += Mb[(long)(i + 0) * NN + j];
        s1 += Mb[(long)(i + 1) * NN + j];
        s2 += Mb[(long)(i + 2) * NN + j];
        s3 += Mb[(long)(i + 3) * NN + j];
    }
    float s = (s0 + s1) + (s2 + s3);
    s -= Mb[(long)j * NN + j];   // exclude diagonal junk term
    inv[blockIdx.y * NN + j] = 1.f / s;
}

// ---------------------------------------------------------------------------
// Fused: normalize exp-Aw (write back fp32, diag=0) + transpose + bf16 split.
// ---------------------------------------------------------------------------
__global__ __launch_bounds__(256) void normtsplit_k(float* __restrict__ Aw,
    const float* __restrict__ inv,
    __nv_bfloat16* __restrict__ oh, __nv_bfloat16* __restrict__ ol)
{
    __shared__ float t[32][33];
    const long nn = (long)NN * NN;
    float* Mb = Aw + (long)blockIdx.z * nn;
    const float* ib = inv + (long)blockIdx.z * NN;
    int r0 = blockIdx.y * 32, c0 = blockIdx.x * 32;
    int tx = threadIdx.x, ty = threadIdx.y;
    const float sc = ib[c0 + tx];
#pragma unroll
    for (int i = 0; i < 4; i++) {
        int r = r0 + ty + i * 8;
        long o = (long)r * NN + c0 + tx;
        float v = Mb[o] * sc;
        if (r == c0 + tx) v = 0.f;
        Mb[o] = v;
        t[ty + i * 8][tx] = v;
    }
    __syncthreads();
    long ob = (long)blockIdx.z * nn;
#pragma unroll
    for (int i = 0; i < 4; i++) {
        float v = t[tx][ty + i * 8];
        __nv_bfloat16 h = __float2bfloat16(v);
        __nv_bfloat16 l = __float2bfloat16(v - __bfloat162float(h));
        long o = ob + (long)(c0 + ty + i * 8) * NN + r0 + tx;
        oh[o] = h; ol[o] = l;
    }
}

// ---------------------------------------------------------------------------
// bf16 transpose (hi & lo in one pass): out[c][r] = in[r][c]
// ---------------------------------------------------------------------------
__global__ __launch_bounds__(256) void tbf16_k(
    const __nv_bfloat16* __restrict__ ih, const __nv_bfloat16* __restrict__ il,
    __nv_bfloat16* __restrict__ oh, __nv_bfloat16* __restrict__ ol,
    int R, int C, int ldin, long sIn, long sOut)
{
    __shared__ __nv_bfloat16 th[32][33], tl[32][33];
    long ibo = (long)blockIdx.z * sIn;
    int r0 = blockIdx.y * 32, c0 = blockIdx.x * 32;
    int tx = threadIdx.x, ty = threadIdx.y;
#pragma unroll
    for (int i = 0; i < 4; i++) {
        long o = ibo + (long)(r0 + ty + i * 8) * ldin + c0 + tx;
        th[ty + i * 8][tx] = ih[o];
        tl[ty + i * 8][tx] = il[o];
    }
    __syncthreads();
    long ob = (long)blockIdx.z * sOut;
#pragma unroll
    for (int i = 0; i < 4; i++) {
        long o = ob + (long)(c0 + ty + i * 8) * R + r0 + tx;
        oh[o] = th[tx][ty + i * 8];
        ol[o] = tl[tx][ty + i * 8];
    }
}

// ---------------------------------------------------------------------------
extern "C" void kernel_launch(void* const* d_in, const int* in_sizes, int n_in,
                              void* d_out, int out_size)
{
    const float* y  = (const float*)d_in[0];
    const float* Wk = (const float*)d_in[1];
    const float* Wq = (const float*)d_in[2];
    const float* Wv = (const float*)d_in[3];
    const float* Wo = (const float*)d_in[4];

    float* out = (float*)d_out;
    float* Aw  = out + (long)BB * NN * DD;

    __nv_bfloat16 *yh, *yl, *Wh, *Wl, *Ph, *Pl, *VTh, *VTl, *ATh, *ATl;
    float* inv;
    cudaGetSymbolAddress((void**)&yh, g_yh);   cudaGetSymbolAddress((void**)&yl, g_yl);
    cudaGetSymbolAddress((void**)&Wh, g_Wh);   cudaGetSymbolAddress((void**)&Wl, g_Wl);
    cudaGetSymbolAddress((void**)&Ph, g_Ph);   cudaGetSymbolAddress((void**)&Pl, g_Pl);
    cudaGetSymbolAddress((void**)&VTh, g_VTh); cudaGetSymbolAddress((void**)&VTl, g_VTl);
    cudaGetSymbolAddress((void**)&ATh, g_ATh); cudaGetSymbolAddress((void**)&ATl, g_ATl);
    cudaGetSymbolAddress((void**)&inv, g_inv);

    cudaFuncSetAttribute(gemm_hmma, cudaFuncAttributeMaxDynamicSharedMemorySize, SMEMB);

    const long nd = (long)NN * DD;
    const long np = (long)NN * PP;
    const long nn = (long)NN * NN;
    const long dd = (long)DD * DD;
    const long nY = (long)BB * NN * DD;

    // 1) splits: Wk / 0.1Wq / Wo (one launch), Wv transposed-split, y split
    {
        dim3 gw((unsigned)(dd / 1024), 1, 3);
        splitW_k<<<gw, 256>>>(Wk, Wq, Wo, Wh, Wl);
        dim3 gt(DD / 32, DD / 32, 1);
        tsplit_k<<<gt, dim3(32, 8)>>>(Wv, Wh + 4 * dd, Wl + 4 * dd, DD, DD);  // Wv^T
        splitf_k<<<(int)(nY / 1024), 256>>>(y, yh, yl, nY);
    }

    // 2) W3 = Wo @ Wv  (A = Wo slot3, B = Wv^T slot4) -> slot 2, bf16 split
    {
        dim3 g(DD / 128, DD / 128, 1);
        gemm_hmma<<<g, 256, SMEMB>>>(Wh + 3 * dd, Wl + 3 * dd, Wh + 4 * dd, Wl + 4 * dd,
                                     nullptr, Wh + 2 * dd, Wl + 2 * dd,
                                     DD, DD, DD, DD, 0, 0, 0, 1.0f, 1);
    }

    // 3) fused projection: P[8192,6144] = y @ [Wk; 0.1Wq; W3]^T -> bf16 split
    //    (P slices: K | Q | VW  where VW = V @ Wo^T)
    {
        dim3 g(PP / 128, (BB * NN) / 128, 1);
        gemm_hmma<<<g, 256, SMEMB>>>(yh, yl, Wh, Wl, nullptr, Ph, Pl,
                                     PP, DD, DD, DD, 0, 0, 0, 1.0f, 1);
    }

    // 4) logits per batch with fused exp: Aw[b] = exp(Q_b @ K_b^T) (fp32)
    {
        dim3 g(NN / 128, NN / 128, BB);
        gemm_hmma<<<g, 256, SMEMB>>>(Ph + DD, Pl + DD, Ph, Pl, Aw, nullptr, nullptr,
                                     NN, DD, PP, PP, np, np, nn, 1.0f, 2);
    }

    // 5) VW transpose (bf16 hi/lo direct): VT[b][d][j] = VW[b][j][d]
    {
        dim3 g2(DD / 32, NN / 32, BB);
        tbf16_k<<<g2, dim3(32, 8)>>>(Ph + 2 * DD, Pl + 2 * DD, VTh, VTl,
                                     NN, DD, PP, np, nd);
    }

    // 6) column sums (diag excluded) -> inv
    {
        dim3 g(NN / 256, BB, 1);
        colsum_k<<<g, 256>>>(Aw, inv);
    }

    // 7) fused normalize (writeback, diag=0) + transpose + bf16 split -> AT
    {
        dim3 g(NN / 32, NN / 32, BB);
        normtsplit_k<<<g, dim3(32, 8)>>>(Aw, inv, ATh, ATl);
    }

    // 8) out[b] = AT_b @ VT_b^T  (fp32 straight into d_out; no Wo GEMM needed)
    {
        dim3 g(DD / 128, NN / 128, BB);
        gemm_hmma<<<g, 256, SMEMB>>>(ATh, ATl, VTh, VTl, out, nullptr, nullptr,
                                     DD, NN, NN, NN, nn, nd, nd, 1.0f, 0);
    }
}

// round 10
// speedup vs baseline: 1.4914x; 1.1668x over previous
#include <cuda_runtime.h>
#include <cuda_bf16.h>
#include <cstdint>
#include <cfloat>
#include <math.h>

#define BB 8
#define NN 1024
#define DD 2048

// ---------------------------------------------------------------------------
// Scratch (allocation-free rule: static __device__ arrays)
// W slots: 0=0.1*Wq^T, 1=Wk^T, 2=Wv^T, 3=Wo, 4=G(=0.1 Wq^T Wk), 5=W3(=Wo@Wv)
// ---------------------------------------------------------------------------
static __device__ __align__(16) __nv_bfloat16 g_yh[BB * NN * DD], g_yl[BB * NN * DD];
static __device__ __align__(16) __nv_bfloat16 g_Wh[6 * DD * DD], g_Wl[6 * DD * DD];
static __device__ __align__(16) __nv_bfloat16 g_VWh[BB * NN * DD], g_VWl[BB * NN * DD];
static __device__ __align__(16) __nv_bfloat16 g_Uh[BB * NN * DD],  g_Ul[BB * NN * DD];
static __device__ __align__(16) __nv_bfloat16 g_VTh[BB * NN * DD], g_VTl[BB * NN * DD];
static __device__ __align__(16) __nv_bfloat16 g_ATh[BB * NN * NN], g_ATl[BB * NN * NN];
static __device__ __align__(16) float         g_inv[BB * NN];

// ---------------------------------------------------------------------------
// Baseline-PTX helpers (sm_103 non-'a': mma.sync / ldmatrix / cp.async)
// ---------------------------------------------------------------------------
__device__ __forceinline__ uint32_t smem_u32(const void* p) {
    uint32_t a;
    asm("{ .reg .u64 t; cvta.to.shared.u64 t, %1; cvt.u32.u64 %0, t; }" : "=r"(a) : "l"(p));
    return a;
}
__device__ __forceinline__ void cp16(uint32_t dst, const void* src) {
    asm volatile("cp.async.cg.shared.global [%0], [%1], 16;" :: "r"(dst), "l"(src) : "memory");
}
#define CP_COMMIT() asm volatile("cp.async.commit_group;" ::: "memory")
#define CP_WAIT1()  asm volatile("cp.async.wait_group 1;" ::: "memory")

__device__ __forceinline__ void ldm_x4(uint32_t& r0, uint32_t& r1, uint32_t& r2, uint32_t& r3,
                                       uint32_t addr) {
    asm volatile("ldmatrix.sync.aligned.m8n8.x4.shared.b16 {%0,%1,%2,%3}, [%4];"
                 : "=r"(r0), "=r"(r1), "=r"(r2), "=r"(r3) : "r"(addr));
}
__device__ __forceinline__ void mma_bf16(float* c, const uint32_t* a, const uint32_t* b) {
    asm volatile(
        "mma.sync.aligned.m16n8k16.row.col.f32.bf16.bf16.f32 "
        "{%0,%1,%2,%3}, {%4,%5,%6,%7}, {%8,%9}, {%0,%1,%2,%3};"
        : "+f"(c[0]), "+f"(c[1]), "+f"(c[2]), "+f"(c[3])
        : "r"(a[0]), "r"(a[1]), "r"(a[2]), "r"(a[3]), "r"(b[0]), "r"(b[1]));
}

// ---------------------------------------------------------------------------
// HMMA GEMM (R6 measured-best core):  C = alpha * A[M,K] * B[Nc,K]^T
// tile 128x128x32, 256 threads (8 warps, 64x32), 3-stage cp.async,
// ONE __syncthreads per stage, XOR-swizzled 64B rows, 2 CTAs/SM.
// mode 0: fp32 C.  mode 1: bf16 hi/lo split C.  mode 2: fp32 exp(C).
// ---------------------------------------------------------------------------
#define MATB   8192               // 128 rows x 64 B
#define STAGEB (4 * MATB)         // Ah, Al, Bh, Bl = 32768 B
#define NSTG   3
#define SMEMB  (NSTG * STAGEB)    // 98304 B

__global__ __launch_bounds__(256, 2) void gemm_hmma(
    const __nv_bfloat16* __restrict__ Ah, const __nv_bfloat16* __restrict__ Al,
    const __nv_bfloat16* __restrict__ Bh, const __nv_bfloat16* __restrict__ Bl,
    float* __restrict__ Cf, __nv_bfloat16* __restrict__ Ch, __nv_bfloat16* __restrict__ Cl,
    int Nc, int K, int lda, int ldb, long sA, long sB, long sC, float alpha, int mode)
{
    extern __shared__ char smem[];
    const uint32_t sb = smem_u32(smem);

    const int tid  = threadIdx.x;
    const int wid  = tid >> 5;
    const int lane = tid & 31;
    const int m0 = blockIdx.y * 128, n0 = blockIdx.x * 128;

    const __nv_bfloat16* pA[2] = { Ah + (long)blockIdx.z * sA + (long)m0 * lda,
                                   Al + (long)blockIdx.z * sA + (long)m0 * lda };
    const __nv_bfloat16* pB[2] = { Bh + (long)blockIdx.z * sB + (long)n0 * ldb,
                                   Bl + (long)blockIdx.z * sB + (long)n0 * ldb };
    const long zC = (long)blockIdx.z * sC;

    const int r0c = tid >> 2, q0 = tid & 3;
    const int r1c = r0c + 64, q1 = q0;
    const int d0 = r0c * 64 + ((q0 ^ ((r0c >> 1) & 3)) * 16);
    const int d1 = r1c * 64 + ((q1 ^ ((r1c >> 1) & 3)) * 16);

    const int wm0 = (wid >> 2) * 64;
    const int wn0 = (wid & 3) * 32;

    const int ra = wm0 + (lane & 15);
    const int qa = (lane >> 4);
    const int rb = wn0 + ((lane >> 3) & 2) * 4 + (lane & 7);
    const int qb = ((lane >> 3) & 1);
    const int sa  = (ra >> 1) & 3;
    const int sbw = (rb >> 1) & 3;

    float acc[4][4][4];
#pragma unroll
    for (int i = 0; i < 4; i++)
#pragma unroll
        for (int j = 0; j < 4; j++)
#pragma unroll
            for (int k = 0; k < 4; k++) acc[i][j][k] = 0.f;

    const int nst = K >> 5;

#pragma unroll
    for (int pc = 0; pc < 2; pc++) {
        const int k0 = pc << 5;
        uint32_t s0 = sb + pc * STAGEB;
#pragma unroll
        for (int m = 0; m < 2; m++) {
            cp16(s0 + m * MATB + d0, pA[m] + (long)r0c * lda + k0 + q0 * 8);
            cp16(s0 + m * MATB + d1, pA[m] + (long)r1c * lda + k0 + q1 * 8);
            cp16(s0 + (2 + m) * MATB + d0, pB[m] + (long)r0c * ldb + k0 + q0 * 8);
            cp16(s0 + (2 + m) * MATB + d1, pB[m] + (long)r1c * ldb + k0 + q1 * 8);
        }
        CP_COMMIT();
    }

    int slot = 0, nslot = 2;
    for (int c = 0; c < nst; c++) {
        CP_WAIT1();
        __syncthreads();

        if (c + 2 < nst) {
            const int k0 = (c + 2) << 5;
            uint32_t s1 = sb + nslot * STAGEB;
#pragma unroll
            for (int m = 0; m < 2; m++) {
                cp16(s1 + m * MATB + d0, pA[m] + (long)r0c * lda + k0 + q0 * 8);
                cp16(s1 + m * MATB + d1, pA[m] + (long)r1c * lda + k0 + q1 * 8);
                cp16(s1 + (2 + m) * MATB + d0, pB[m] + (long)r0c * ldb + k0 + q0 * 8);
                cp16(s1 + (2 + m) * MATB + d1, pB[m] + (long)r1c * ldb + k0 + q1 * 8);
            }
        }
        CP_COMMIT();
        if (++nslot == NSTG) nslot = 0;

        const uint32_t st = sb + slot * STAGEB;
        if (++slot == NSTG) slot = 0;

#pragma unroll
        for (int s = 0; s < 2; s++) {
            const int qla = (s * 2 + qa) ^ sa;
            const int qlb = (s * 2 + qb) ^ sbw;
            const uint32_t aHb = st + 0 * MATB + ra * 64 + qla * 16;
            const uint32_t aLb = st + 1 * MATB + ra * 64 + qla * 16;
            const uint32_t bHb = st + 2 * MATB + rb * 64 + qlb * 16;
            const uint32_t bLb = st + 3 * MATB + rb * 64 + qlb * 16;

            uint32_t bh[2][4], bl[2][4];
#pragma unroll
            for (int nb = 0; nb < 2; nb++) {
                ldm_x4(bh[nb][0], bh[nb][1], bh[nb][2], bh[nb][3], bHb + nb * 1024);
                ldm_x4(bl[nb][0], bl[nb][1], bl[nb][2], bl[nb][3], bLb + nb * 1024);
            }
#pragma unroll
            for (int mi = 0; mi < 4; mi++) {
                uint32_t ah[4], al[4];
                ldm_x4(ah[0], ah[1], ah[2], ah[3], aHb + mi * 1024);
                ldm_x4(al[0], al[1], al[2], al[3], aLb + mi * 1024);
#pragma unroll
                for (int ni = 0; ni < 4; ni++) {
                    const uint32_t* bhf = &bh[ni >> 1][(ni & 1) * 2];
                    const uint32_t* blf = &bl[ni >> 1][(ni & 1) * 2];
                    mma_bf16(acc[mi][ni], ah, bhf);
                    mma_bf16(acc[mi][ni], ah, blf);
                    mma_bf16(acc[mi][ni], al, bhf);
                }
            }
        }
    }

    const int er = lane >> 2;
    const int ec = (lane & 3) * 2;
#pragma unroll
    for (int mi = 0; mi < 4; mi++) {
#pragma unroll
        for (int ni = 0; ni < 4; ni++) {
            const int row = m0 + wm0 + 16 * mi + er;
            const int col = n0 + wn0 + 8 * ni + ec;
            float v0 = acc[mi][ni][0] * alpha, v1 = acc[mi][ni][1] * alpha;
            float v2 = acc[mi][ni][2] * alpha, v3 = acc[mi][ni][3] * alpha;
            if (mode == 0) {
                *reinterpret_cast<float2*>(Cf + zC + (long)row * Nc + col) = make_float2(v0, v1);
                *reinterpret_cast<float2*>(Cf + zC + (long)(row + 8) * Nc + col) = make_float2(v2, v3);
            } else if (mode == 2) {
                *reinterpret_cast<float2*>(Cf + zC + (long)row * Nc + col) =
                    make_float2(__expf(v0), __expf(v1));
                *reinterpret_cast<float2*>(Cf + zC + (long)(row + 8) * Nc + col) =
                    make_float2(__expf(v2), __expf(v3));
            } else {
                __nv_bfloat162 h, l;
                h.x = __float2bfloat16(v0); l.x = __float2bfloat16(v0 - __bfloat162float(h.x));
                h.y = __float2bfloat16(v1); l.y = __float2bfloat16(v1 - __bfloat162float(h.y));
                *reinterpret_cast<__nv_bfloat162*>(Ch + zC + (long)row * Nc + col) = h;
                *reinterpret_cast<__nv_bfloat162*>(Cl + zC + (long)row * Nc + col) = l;
                h.x = __float2bfloat16(v2); l.x = __float2bfloat16(v2 - __bfloat162float(h.x));
                h.y = __float2bfloat16(v3); l.y = __float2bfloat16(v3 - __bfloat162float(h.y));
                *reinterpret_cast<__nv_bfloat162*>(Ch + zC + (long)(row + 8) * Nc + col) = h;
                *reinterpret_cast<__nv_bfloat162*>(Cl + zC + (long)(row + 8) * Nc + col) = l;
            }
        }
    }
}

// ---------------------------------------------------------------------------
// fp32 -> bf16 hi/lo elementwise split
// ---------------------------------------------------------------------------
__global__ __launch_bounds__(256) void splitf_k(const float* __restrict__ x,
    __nv_bfloat16* __restrict__ hi, __nv_bfloat16* __restrict__ lo, long n)
{
    long i = ((long)blockIdx.x * 256 + threadIdx.x) * 4;
    if (i >= n) return;
    float4 v = *reinterpret_cast<const float4*>(x + i);
    __nv_bfloat162 h01, h23, l01, l23;
    h01.x = __float2bfloat16(v.x); l01.x = __float2bfloat16(v.x - __bfloat162float(h01.x));
    h01.y = __float2bfloat16(v.y); l01.y = __float2bfloat16(v.y - __bfloat162float(h01.y));
    h23.x = __float2bfloat16(v.z); l23.x = __float2bfloat16(v.z - __bfloat162float(h23.x));
    h23.y = __float2bfloat16(v.w); l23.y = __float2bfloat16(v.w - __bfloat162float(h23.y));
    uint2 hv, lv;
    hv.x = *reinterpret_cast<uint32_t*>(&h01); hv.y = *reinterpret_cast<uint32_t*>(&h23);
    lv.x = *reinterpret_cast<uint32_t*>(&l01); lv.y = *reinterpret_cast<uint32_t*>(&l23);
    *reinterpret_cast<uint2*>(hi + i) = hv;
    *reinterpret_cast<uint2*>(lo + i) = lv;
}

// ---------------------------------------------------------------------------
// transpose + scale + split fp32 -> bf16 hi/lo: out[c][r] = split(s*in[r][c])
// ---------------------------------------------------------------------------
__global__ __launch_bounds__(256) void tsplit_k(const float* __restrict__ in,
    __nv_bfloat16* __restrict__ oh, __nv_bfloat16* __restrict__ ol,
    int R, int C, float scale)
{
    __shared__ float t[32][33];
    int r0 = blockIdx.y * 32, c0 = blockIdx.x * 32;
    int tx = threadIdx.x, ty = threadIdx.y;
#pragma unroll
    for (int i = 0; i < 4; i++)
        t[ty + i * 8][tx] = in[(long)(r0 + ty + i * 8) * C + c0 + tx] * scale;
    __syncthreads();
#pragma unroll
    for (int i = 0; i < 4; i++) {
        float v = t[tx][ty + i * 8];
        __nv_bfloat16 h = __float2bfloat16(v);
        __nv_bfloat16 l = __float2bfloat16(v - __bfloat162float(h));
        long o = (long)(c0 + ty + i * 8) * R + r0 + tx;
        oh[o] = h; ol[o] = l;
    }
}

// ---------------------------------------------------------------------------
// Column sums of exp-logits (diag excluded) -> inv[b][j] = 1/sum
// ---------------------------------------------------------------------------
__global__ __launch_bounds__(256) void colsum_k(const float* __restrict__ Aw,
                                                float* __restrict__ inv)
{
    const int j = blockIdx.x * blockDim.x + threadIdx.x;
    const float* Mb = Aw + (long)blockIdx.y * NN * NN;
    float s0 = 0.f, s1 = 0.f, s2 = 0.f, s3 = 0.f;
#pragma unroll 4
    for (int i = 0; i < NN; i += 4) {
        s0 += Mb[(long)(i + 0) * NN + j];
        s1 += Mb[(long)(i + 1) * NN + j];
        s2 += Mb[(long)(i + 2) * NN + j];
        s3 += Mb[(long)(i + 3) * NN + j];
    }
    float s = (s0 + s1) + (s2 + s3);
    s -= Mb[(long)j * NN + j];   // exclude diagonal junk term
    inv[blockIdx.y * NN + j] = 1.f / s;
}

// ---------------------------------------------------------------------------
// Fused: normalize exp-Aw (write back fp32, diag=0) + transpose + bf16 split.
// ---------------------------------------------------------------------------
__global__ __launch_bounds__(256) void normtsplit_k(float* __restrict__ Aw,
    const float* __restrict__ inv,
    __nv_bfloat16* __restrict__ oh, __nv_bfloat16* __restrict__ ol)
{
    __shared__ float t[32][33];
    const long nn = (long)NN * NN;
    float* Mb = Aw + (long)blockIdx.z * nn;
    const float* ib = inv + (long)blockIdx.z * NN;
    int r0 = blockIdx.y * 32, c0 = blockIdx.x * 32;
    int tx = threadIdx.x, ty = threadIdx.y;
    const float sc = ib[c0 + tx];
#pragma unroll
    for (int i = 0; i < 4; i++) {
        int r = r0 + ty + i * 8;
        long o = (long)r * NN + c0 + tx;
        float v = Mb[o] * sc;
        if (r == c0 + tx) v = 0.f;
        Mb[o] = v;
        t[ty + i * 8][tx] = v;
    }
    __syncthreads();
    long ob = (long)blockIdx.z * nn;
#pragma unroll
    for (int i = 0; i < 4; i++) {
        float v = t[tx][ty + i * 8];
        __nv_bfloat16 h = __float2bfloat16(v);
        __nv_bfloat16 l = __float2bfloat16(v - __bfloat162float(h));
        long o = ob + (long)(c0 + ty + i * 8) * NN + r0 + tx;
        oh[o] = h; ol[o] = l;
    }
}

// ---------------------------------------------------------------------------
// bf16 transpose (hi & lo in one pass): out[c][r] = in[r][c]
// ---------------------------------------------------------------------------
__global__ __launch_bounds__(256) void tbf16_k(
    const __nv_bfloat16* __restrict__ ih, const __nv_bfloat16* __restrict__ il,
    __nv_bfloat16* __restrict__ oh, __nv_bfloat16* __restrict__ ol,
    int R, int C, int ldin, long sIn, long sOut)
{
    __shared__ __nv_bfloat16 th[32][33], tl[32][33];
    long ibo = (long)blockIdx.z * sIn;
    int r0 = blockIdx.y * 32, c0 = blockIdx.x * 32;
    int tx = threadIdx.x, ty = threadIdx.y;
#pragma unroll
    for (int i = 0; i < 4; i++) {
        long o = ibo + (long)(r0 + ty + i * 8) * ldin + c0 + tx;
        th[ty + i * 8][tx] = ih[o];
        tl[ty + i * 8][tx] = il[o];
    }
    __syncthreads();
    long ob = (long)blockIdx.z * sOut;
#pragma unroll
    for (int i = 0; i < 4; i++) {
        long o = ob + (long)(c0 + ty + i * 8) * R + r0 + tx;
        oh[o] = th[tx][ty + i * 8];
        ol[o] = tl[tx][ty + i * 8];
    }
}

// ---------------------------------------------------------------------------
extern "C" void kernel_launch(void* const* d_in, const int* in_sizes, int n_in,
                              void* d_out, int out_size)
{
    const float* y  = (const float*)d_in[0];
    const float* Wk = (const float*)d_in[1];
    const float* Wq = (const float*)d_in[2];
    const float* Wv = (const float*)d_in[3];
    const float* Wo = (const float*)d_in[4];

    float* out = (float*)d_out;
    float* Aw  = out + (long)BB * NN * DD;

    __nv_bfloat16 *yh, *yl, *Wh, *Wl, *VWh, *VWl, *Uh, *Ul, *VTh, *VTl, *ATh, *ATl;
    float* inv;
    cudaGetSymbolAddress((void**)&yh, g_yh);   cudaGetSymbolAddress((void**)&yl, g_yl);
    cudaGetSymbolAddress((void**)&Wh, g_Wh);   cudaGetSymbolAddress((void**)&Wl, g_Wl);
    cudaGetSymbolAddress((void**)&VWh, g_VWh); cudaGetSymbolAddress((void**)&VWl, g_VWl);
    cudaGetSymbolAddress((void**)&Uh, g_Uh);   cudaGetSymbolAddress((void**)&Ul, g_Ul);
    cudaGetSymbolAddress((void**)&VTh, g_VTh); cudaGetSymbolAddress((void**)&VTl, g_VTl);
    cudaGetSymbolAddress((void**)&ATh, g_ATh); cudaGetSymbolAddress((void**)&ATl, g_ATl);
    cudaGetSymbolAddress((void**)&inv, g_inv);

    cudaFuncSetAttribute(gemm_hmma, cudaFuncAttributeMaxDynamicSharedMemorySize, SMEMB);

    const long nd = (long)NN * DD;
    const long nn = (long)NN * NN;
    const long dd = (long)DD * DD;
    const long nY = (long)BB * NN * DD;

    // 1) operand prep: transposed splits of Wq(0.1)/Wk/Wv, plain splits of Wo, y
    {
        dim3 gt(DD / 32, DD / 32, 1);
        tsplit_k<<<gt, dim3(32, 8)>>>(Wq, Wh + 0 * dd, Wl + 0 * dd, DD, DD, 0.1f); // 0.1*Wq^T
        tsplit_k<<<gt, dim3(32, 8)>>>(Wk, Wh + 1 * dd, Wl + 1 * dd, DD, DD, 1.0f); // Wk^T
        tsplit_k<<<gt, dim3(32, 8)>>>(Wv, Wh + 2 * dd, Wl + 2 * dd, DD, DD, 1.0f); // Wv^T
        splitf_k<<<(int)(dd / 1024), 256>>>(Wo, Wh + 3 * dd, Wl + 3 * dd, dd);     // Wo
        splitf_k<<<(int)(nY / 1024), 256>>>(y, yh, yl, nY);
    }

    // 2) G = (0.1 Wq^T) @ Wk  : C[i,j] = sum_e WqT[i,e] * WkT[j,e]  -> slot 4
    {
        dim3 g(DD / 128, DD / 128, 1);
        gemm_hmma<<<g, 256, SMEMB>>>(Wh + 0 * dd, Wl + 0 * dd, Wh + 1 * dd, Wl + 1 * dd,
                                     nullptr, Wh + 4 * dd, Wl + 4 * dd,
                                     DD, DD, DD, DD, 0, 0, 0, 1.0f, 1);
    }

    // 3) W3 = Wo @ Wv  (A = Wo, B = Wv^T) -> slot 5
    {
        dim3 g(DD / 128, DD / 128, 1);
        gemm_hmma<<<g, 256, SMEMB>>>(Wh + 3 * dd, Wl + 3 * dd, Wh + 2 * dd, Wl + 2 * dd,
                                     nullptr, Wh + 5 * dd, Wl + 5 * dd,
                                     DD, DD, DD, DD, 0, 0, 0, 1.0f, 1);
    }

    // 4) U = y_flat @ G : U[j,d] = sum_d' y[j,d'] * G[d,d']  -> bf16 split
    {
        dim3 g(DD / 128, (BB * NN) / 128, 1);
        gemm_hmma<<<g, 256, SMEMB>>>(yh, yl, Wh + 4 * dd, Wl + 4 * dd, nullptr, Uh, Ul,
                                     DD, DD, DD, DD, 0, 0, 0, 1.0f, 1);
    }

    // 5) VW = y_flat @ W3^T  (VW = V @ Wo^T)  -> bf16 split
    {
        dim3 g(DD / 128, (BB * NN) / 128, 1);
        gemm_hmma<<<g, 256, SMEMB>>>(yh, yl, Wh + 5 * dd, Wl + 5 * dd, nullptr, VWh, VWl,
                                     DD, DD, DD, DD, 0, 0, 0, 1.0f, 1);
    }

    // 6) logits per batch with fused exp: Aw[b] = exp(y[b] @ U[b]^T)
    //    logits[i,j] = sum_d y[i,d] * U[j,d]  ( = 0.1 * Q.K^T )
    {
        dim3 g(NN / 128, NN / 128, BB);
        gemm_hmma<<<g, 256, SMEMB>>>(yh, yl, Uh, Ul, Aw, nullptr, nullptr,
                                     NN, DD, DD, DD, nd, nd, nn, 1.0f, 2);
    }

    // 7) VW transpose (bf16 hi/lo direct): VT[b][d][j] = VW[b][j][d]
    {
        dim3 g2(DD / 32, NN / 32, BB);
        tbf16_k<<<g2, dim3(32, 8)>>>(VWh, VWl, VTh, VTl, NN, DD, DD, nd, nd);
    }

    // 8) column sums (diag excluded) -> inv
    {
        dim3 g(NN / 256, BB, 1);
        colsum_k<<<g, 256>>>(Aw, inv);
    }

    // 9) fused normalize (writeback, diag=0) + transpose + bf16 split -> AT
    {
        dim3 g(NN / 32, NN / 32, BB);
        normtsplit_k<<<g, dim3(32, 8)>>>(Aw, inv, ATh, ATl);
    }

    // 10) out[b] = AT_b @ VT_b^T  (fp32 straight into d_out)
    {
        dim3 g(DD / 128, NN / 128, BB);
        gemm_hmma<<<g, 256, SMEMB>>>(ATh, ATl, VTh, VTl, out, nullptr, nullptr,
                                     DD, NN, NN, NN, nn, nd, nd, 1.0f, 0);
    }
}

// round 11
// speedup vs baseline: 1.5078x; 1.0110x over previous
#include <cuda_runtime.h>
#include <cuda_bf16.h>
#include <cstdint>
#include <cfloat>
#include <math.h>

#define BB 8
#define NN 1024
#define DD 2048
#define UW (2 * DD)   // fused U|VW width

// ---------------------------------------------------------------------------
// Scratch (allocation-free rule: static __device__ arrays)
// W slots: 0=0.1*Wq^T, 1=Wo, 2=Wk^T, 3=Wv^T, 4=G(=0.1 Wq^T Wk), 5=W3(=Wo@Wv)
// (layout chosen so the G/W3 GEMMs batch via blockIdx.z, and [G;W3] is a
//  contiguous 4096-row B operand for the fused U|VW GEMM)
// ---------------------------------------------------------------------------
static __device__ __align__(16) __nv_bfloat16 g_yh[BB * NN * DD], g_yl[BB * NN * DD];
static __device__ __align__(16) __nv_bfloat16 g_Wh[6 * DD * DD], g_Wl[6 * DD * DD];
static __device__ __align__(16) __nv_bfloat16 g_UVWh[BB * NN * UW], g_UVWl[BB * NN * UW];
static __device__ __align__(16) __nv_bfloat16 g_VTh[BB * NN * DD], g_VTl[BB * NN * DD];
static __device__ __align__(16) __nv_bfloat16 g_ATh[BB * NN * NN], g_ATl[BB * NN * NN];
static __device__ __align__(16) float         g_inv[BB * NN];

// ---------------------------------------------------------------------------
// Baseline-PTX helpers (sm_103 non-'a': mma.sync / ldmatrix / cp.async)
// ---------------------------------------------------------------------------
__device__ __forceinline__ uint32_t smem_u32(const void* p) {
    uint32_t a;
    asm("{ .reg .u64 t; cvta.to.shared.u64 t, %1; cvt.u32.u64 %0, t; }" : "=r"(a) : "l"(p));
    return a;
}
__device__ __forceinline__ void cp16(uint32_t dst, const void* src) {
    asm volatile("cp.async.cg.shared.global [%0], [%1], 16;" :: "r"(dst), "l"(src) : "memory");
}
#define CP_COMMIT() asm volatile("cp.async.commit_group;" ::: "memory")
#define CP_WAIT1()  asm volatile("cp.async.wait_group 1;" ::: "memory")

__device__ __forceinline__ void ldm_x4(uint32_t& r0, uint32_t& r1, uint32_t& r2, uint32_t& r3,
                                       uint32_t addr) {
    asm volatile("ldmatrix.sync.aligned.m8n8.x4.shared.b16 {%0,%1,%2,%3}, [%4];"
                 : "=r"(r0), "=r"(r1), "=r"(r2), "=r"(r3) : "r"(addr));
}
__device__ __forceinline__ void mma_bf16(float* c, const uint32_t* a, const uint32_t* b) {
    asm volatile(
        "mma.sync.aligned.m16n8k16.row.col.f32.bf16.bf16.f32 "
        "{%0,%1,%2,%3}, {%4,%5,%6,%7}, {%8,%9}, {%0,%1,%2,%3};"
        : "+f"(c[0]), "+f"(c[1]), "+f"(c[2]), "+f"(c[3])
        : "r"(a[0]), "r"(a[1]), "r"(a[2]), "r"(a[3]), "r"(b[0]), "r"(b[1]));
}

// ---------------------------------------------------------------------------
// HMMA GEMM (R6 measured-best core):  C = alpha * A[M,K] * B[Nc,K]^T
// tile 128x128x32, 256 threads (8 warps, 64x32), 3-stage cp.async,
// ONE __syncthreads per stage, XOR-swizzled 64B rows, 2 CTAs/SM.
// mode 0: fp32 C.  mode 1: bf16 hi/lo split C.  mode 2: fp32 exp(C).
// ---------------------------------------------------------------------------
#define MATB   8192               // 128 rows x 64 B
#define STAGEB (4 * MATB)         // Ah, Al, Bh, Bl = 32768 B
#define NSTG   3
#define SMEMB  (NSTG * STAGEB)    // 98304 B

__global__ __launch_bounds__(256, 2) void gemm_hmma(
    const __nv_bfloat16* __restrict__ Ah, const __nv_bfloat16* __restrict__ Al,
    const __nv_bfloat16* __restrict__ Bh, const __nv_bfloat16* __restrict__ Bl,
    float* __restrict__ Cf, __nv_bfloat16* __restrict__ Ch, __nv_bfloat16* __restrict__ Cl,
    int Nc, int K, int lda, int ldb, long sA, long sB, long sC, float alpha, int mode)
{
    extern __shared__ char smem[];
    const uint32_t sb = smem_u32(smem);

    const int tid  = threadIdx.x;
    const int wid  = tid >> 5;
    const int lane = tid & 31;
    const int m0 = blockIdx.y * 128, n0 = blockIdx.x * 128;

    const __nv_bfloat16* pA[2] = { Ah + (long)blockIdx.z * sA + (long)m0 * lda,
                                   Al + (long)blockIdx.z * sA + (long)m0 * lda };
    const __nv_bfloat16* pB[2] = { Bh + (long)blockIdx.z * sB + (long)n0 * ldb,
                                   Bl + (long)blockIdx.z * sB + (long)n0 * ldb };
    const long zC = (long)blockIdx.z * sC;

    const int r0c = tid >> 2, q0 = tid & 3;
    const int r1c = r0c + 64, q1 = q0;
    const int d0 = r0c * 64 + ((q0 ^ ((r0c >> 1) & 3)) * 16);
    const int d1 = r1c * 64 + ((q1 ^ ((r1c >> 1) & 3)) * 16);

    const int wm0 = (wid >> 2) * 64;
    const int wn0 = (wid & 3) * 32;

    const int ra = wm0 + (lane & 15);
    const int qa = (lane >> 4);
    const int rb = wn0 + ((lane >> 3) & 2) * 4 + (lane & 7);
    const int qb = ((lane >> 3) & 1);
    const int sa  = (ra >> 1) & 3;
    const int sbw = (rb >> 1) & 3;

    float acc[4][4][4];
#pragma unroll
    for (int i = 0; i < 4; i++)
#pragma unroll
        for (int j = 0; j < 4; j++)
#pragma unroll
            for (int k = 0; k < 4; k++) acc[i][j][k] = 0.f;

    const int nst = K >> 5;

#pragma unroll
    for (int pc = 0; pc < 2; pc++) {
        const int k0 = pc << 5;
        uint32_t s0 = sb + pc * STAGEB;
#pragma unroll
        for (int m = 0; m < 2; m++) {
            cp16(s0 + m * MATB + d0, pA[m] + (long)r0c * lda + k0 + q0 * 8);
            cp16(s0 + m * MATB + d1, pA[m] + (long)r1c * lda + k0 + q1 * 8);
            cp16(s0 + (2 + m) * MATB + d0, pB[m] + (long)r0c * ldb + k0 + q0 * 8);
            cp16(s0 + (2 + m) * MATB + d1, pB[m] + (long)r1c * ldb + k0 + q1 * 8);
        }
        CP_COMMIT();
    }

    int slot = 0, nslot = 2;
    for (int c = 0; c < nst; c++) {
        CP_WAIT1();
        __syncthreads();

        if (c + 2 < nst) {
            const int k0 = (c + 2) << 5;
            uint32_t s1 = sb + nslot * STAGEB;
#pragma unroll
            for (int m = 0; m < 2; m++) {
                cp16(s1 + m * MATB + d0, pA[m] + (long)r0c * lda + k0 + q0 * 8);
                cp16(s1 + m * MATB + d1, pA[m] + (long)r1c * lda + k0 + q1 * 8);
                cp16(s1 + (2 + m) * MATB + d0, pB[m] + (long)r0c * ldb + k0 + q0 * 8);
                cp16(s1 + (2 + m) * MATB + d1, pB[m] + (long)r1c * ldb + k0 + q1 * 8);
            }
        }
        CP_COMMIT();
        if (++nslot == NSTG) nslot = 0;

        const uint32_t st = sb + slot * STAGEB;
        if (++slot == NSTG) slot = 0;

#pragma unroll
        for (int s = 0; s < 2; s++) {
            const int qla = (s * 2 + qa) ^ sa;
            const int qlb = (s * 2 + qb) ^ sbw;
            const uint32_t aHb = st + 0 * MATB + ra * 64 + qla * 16;
            const uint32_t aLb = st + 1 * MATB + ra * 64 + qla * 16;
            const uint32_t bHb = st + 2 * MATB + rb * 64 + qlb * 16;
            const uint32_t bLb = st + 3 * MATB + rb * 64 + qlb * 16;

            uint32_t bh[2][4], bl[2][4];
#pragma unroll
            for (int nb = 0; nb < 2; nb++) {
                ldm_x4(bh[nb][0], bh[nb][1], bh[nb][2], bh[nb][3], bHb + nb * 1024);
                ldm_x4(bl[nb][0], bl[nb][1], bl[nb][2], bl[nb][3], bLb + nb * 1024);
            }
#pragma unroll
            for (int mi = 0; mi < 4; mi++) {
                uint32_t ah[4], al[4];
                ldm_x4(ah[0], ah[1], ah[2], ah[3], aHb + mi * 1024);
                ldm_x4(al[0], al[1], al[2], al[3], aLb + mi * 1024);
                // term-major sweeps: same-acc reuse distance = 4 MMAs
#pragma unroll
                for (int ni = 0; ni < 4; ni++)
                    mma_bf16(acc[mi][ni], ah, &bh[ni >> 1][(ni & 1) * 2]);
#pragma unroll
                for (int ni = 0; ni < 4; ni++)
                    mma_bf16(acc[mi][ni], ah, &bl[ni >> 1][(ni & 1) * 2]);
#pragma unroll
                for (int ni = 0; ni < 4; ni++)
                    mma_bf16(acc[mi][ni], al, &bh[ni >> 1][(ni & 1) * 2]);
            }
        }
    }

    const int er = lane >> 2;
    const int ec = (lane & 3) * 2;
#pragma unroll
    for (int mi = 0; mi < 4; mi++) {
#pragma unroll
        for (int ni = 0; ni < 4; ni++) {
            const int row = m0 + wm0 + 16 * mi + er;
            const int col = n0 + wn0 + 8 * ni + ec;
            float v0 = acc[mi][ni][0] * alpha, v1 = acc[mi][ni][1] * alpha;
            float v2 = acc[mi][ni][2] * alpha, v3 = acc[mi][ni][3] * alpha;
            if (mode == 0) {
                *reinterpret_cast<float2*>(Cf + zC + (long)row * Nc + col) = make_float2(v0, v1);
                *reinterpret_cast<float2*>(Cf + zC + (long)(row + 8) * Nc + col) = make_float2(v2, v3);
            } else if (mode == 2) {
                *reinterpret_cast<float2*>(Cf + zC + (long)row * Nc + col) =
                    make_float2(__expf(v0), __expf(v1));
                *reinterpret_cast<float2*>(Cf + zC + (long)(row + 8) * Nc + col) =
                    make_float2(__expf(v2), __expf(v3));
            } else {
                __nv_bfloat162 h, l;
                h.x = __float2bfloat16(v0); l.x = __float2bfloat16(v0 - __bfloat162float(h.x));
                h.y = __float2bfloat16(v1); l.y = __float2bfloat16(v1 - __bfloat162float(h.y));
                *reinterpret_cast<__nv_bfloat162*>(Ch + zC + (long)row * Nc + col) = h;
                *reinterpret_cast<__nv_bfloat162*>(Cl + zC + (long)row * Nc + col) = l;
                h.x = __float2bfloat16(v2); l.x = __float2bfloat16(v2 - __bfloat162float(h.x));
                h.y = __float2bfloat16(v3); l.y = __float2bfloat16(v3 - __bfloat162float(h.y));
                *reinterpret_cast<__nv_bfloat162*>(Ch + zC + (long)(row + 8) * Nc + col) = h;
                *reinterpret_cast<__nv_bfloat162*>(Cl + zC + (long)(row + 8) * Nc + col) = l;
            }
        }
    }
}

// ---------------------------------------------------------------------------
// fp32 -> bf16 hi/lo elementwise split
// ---------------------------------------------------------------------------
__global__ __launch_bounds__(256) void splitf_k(const float* __restrict__ x,
    __nv_bfloat16* __restrict__ hi, __nv_bfloat16* __restrict__ lo, long n)
{
    long i = ((long)blockIdx.x * 256 + threadIdx.x) * 4;
    if (i >= n) return;
    float4 v = *reinterpret_cast<const float4*>(x + i);
    __nv_bfloat162 h01, h23, l01, l23;
    h01.x = __float2bfloat16(v.x); l01.x = __float2bfloat16(v.x - __bfloat162float(h01.x));
    h01.y = __float2bfloat16(v.y); l01.y = __float2bfloat16(v.y - __bfloat162float(h01.y));
    h23.x = __float2bfloat16(v.z); l23.x = __float2bfloat16(v.z - __bfloat162float(h23.x));
    h23.y = __float2bfloat16(v.w); l23.y = __float2bfloat16(v.w - __bfloat162float(h23.y));
    uint2 hv, lv;
    hv.x = *reinterpret_cast<uint32_t*>(&h01); hv.y = *reinterpret_cast<uint32_t*>(&h23);
    lv.x = *reinterpret_cast<uint32_t*>(&l01); lv.y = *reinterpret_cast<uint32_t*>(&l23);
    *reinterpret_cast<uint2*>(hi + i) = hv;
    *reinterpret_cast<uint2*>(lo + i) = lv;
}

// ---------------------------------------------------------------------------
// transpose + scale + split fp32 -> bf16 hi/lo: out[c][r] = split(s*in[r][c])
// ---------------------------------------------------------------------------
__global__ __launch_bounds__(256) void tsplit_k(const float* __restrict__ in,
    __nv_bfloat16* __restrict__ oh, __nv_bfloat16* __restrict__ ol,
    int R, int C, float scale)
{
    __shared__ float t[32][33];
    int r0 = blockIdx.y * 32, c0 = blockIdx.x * 32;
    int tx = threadIdx.x, ty = threadIdx.y;
#pragma unroll
    for (int i = 0; i < 4; i++)
        t[ty + i * 8][tx] = in[(long)(r0 + ty + i * 8) * C + c0 + tx] * scale;
    __syncthreads();
#pragma unroll
    for (int i = 0; i < 4; i++) {
        float v = t[tx][ty + i * 8];
        __nv_bfloat16 h = __float2bfloat16(v);
        __nv_bfloat16 l = __float2bfloat16(v - __bfloat162float(h));
        long o = (long)(c0 + ty + i * 8) * R + r0 + tx;
        oh[o] = h; ol[o] = l;
    }
}

// ---------------------------------------------------------------------------
// Column sums of exp-logits (diag excluded) -> inv[b][j] = 1/sum
// ---------------------------------------------------------------------------
__global__ __launch_bounds__(256) void colsum_k(const float* __restrict__ Aw,
                                                float* __restrict__ inv)
{
    const int j = blockIdx.x * blockDim.x + threadIdx.x;
    const float* Mb = Aw + (long)blockIdx.y * NN * NN;
    float s0 = 0.f, s1 = 0.f, s2 = 0.f, s3 = 0.f;
#pragma unroll 4
    for (int i = 0; i < NN; i += 4) {
        s0 += Mb[(long)(i + 0) * NN + j];
        s1 += Mb[(long)(i + 1) * NN + j];
        s2 += Mb[(long)(i + 2) * NN + j];
        s3 += Mb[(long)(i + 3) * NN + j];
    }
    float s = (s0 + s1) + (s2 + s3);
    s -= Mb[(long)j * NN + j];   // exclude diagonal junk term
    inv[blockIdx.y * NN + j] = 1.f / s;
}

// ---------------------------------------------------------------------------
// Fused: normalize exp-Aw (write back fp32, diag=0) + transpose + bf16 split.
// ---------------------------------------------------------------------------
__global__ __launch_bounds__(256) void normtsplit_k(float* __restrict__ Aw,
    const float* __restrict__ inv,
    __nv_bfloat16* __restrict__ oh, __nv_bfloat16* __restrict__ ol)
{
    __shared__ float t[32][33];
    const long nn = (long)NN * NN;
    float* Mb = Aw + (long)blockIdx.z * nn;
    const float* ib = inv + (long)blockIdx.z * NN;
    int r0 = blockIdx.y * 32, c0 = blockIdx.x * 32;
    int tx = threadIdx.x, ty = threadIdx.y;
    const float sc = ib[c0 + tx];
#pragma unroll
    for (int i = 0; i < 4; i++) {
        int r = r0 + ty + i * 8;
        long o = (long)r * NN + c0 + tx;
        float v = Mb[o] * sc;
        if (r == c0 + tx) v = 0.f;
        Mb[o] = v;
        t[ty + i * 8][tx] = v;
    }
    __syncthreads();
    long ob = (long)blockIdx.z * nn;
#pragma unroll
    for (int i = 0; i < 4; i++) {
        float v = t[tx][ty + i * 8];
        __nv_bfloat16 h = __float2bfloat16(v);
        __nv_bfloat16 l = __float2bfloat16(v - __bfloat162float(h));
        long o = ob + (long)(c0 + ty + i * 8) * NN + r0 + tx;
        oh[o] = h; ol[o] = l;
    }
}

// ---------------------------------------------------------------------------
// bf16 transpose (hi & lo in one pass): out[c][r] = in[r][c]
// ---------------------------------------------------------------------------
__global__ __launch_bounds__(256) void tbf16_k(
    const __nv_bfloat16* __restrict__ ih, const __nv_bfloat16* __restrict__ il,
    __nv_bfloat16* __restrict__ oh, __nv_bfloat16* __restrict__ ol,
    int R, int C, int ldin, long sIn, long sOut)
{
    __shared__ __nv_bfloat16 th[32][33], tl[32][33];
    long ibo = (long)blockIdx.z * sIn;
    int r0 = blockIdx.y * 32, c0 = blockIdx.x * 32;
    int tx = threadIdx.x, ty = threadIdx.y;
#pragma unroll
    for (int i = 0; i < 4; i++) {
        long o = ibo + (long)(r0 + ty + i * 8) * ldin + c0 + tx;
        th[ty + i * 8][tx] = ih[o];
        tl[ty + i * 8][tx] = il[o];
    }
    __syncthreads();
    long ob = (long)blockIdx.z * sOut;
#pragma unroll
    for (int i = 0; i < 4; i++) {
        long o = ob + (long)(c0 + ty + i * 8) * R + r0 + tx;
        oh[o] = th[tx][ty + i * 8];
        ol[o] = tl[tx][ty + i * 8];
    }
}

// ---------------------------------------------------------------------------
extern "C" void kernel_launch(void* const* d_in, const int* in_sizes, int n_in,
                              void* d_out, int out_size)
{
    const float* y  = (const float*)d_in[0];
    const float* Wk = (const float*)d_in[1];
    const float* Wq = (const float*)d_in[2];
    const float* Wv = (const float*)d_in[3];
    const float* Wo = (const float*)d_in[4];

    float* out = (float*)d_out;
    float* Aw  = out + (long)BB * NN * DD;

    __nv_bfloat16 *yh, *yl, *Wh, *Wl, *UVWh, *UVWl, *VTh, *VTl, *ATh, *ATl;
    float* inv;
    cudaGetSymbolAddress((void**)&yh, g_yh);     cudaGetSymbolAddress((void**)&yl, g_yl);
    cudaGetSymbolAddress((void**)&Wh, g_Wh);     cudaGetSymbolAddress((void**)&Wl, g_Wl);
    cudaGetSymbolAddress((void**)&UVWh, g_UVWh); cudaGetSymbolAddress((void**)&UVWl, g_UVWl);
    cudaGetSymbolAddress((void**)&VTh, g_VTh);   cudaGetSymbolAddress((void**)&VTl, g_VTl);
    cudaGetSymbolAddress((void**)&ATh, g_ATh);   cudaGetSymbolAddress((void**)&ATl, g_ATl);
    cudaGetSymbolAddress((void**)&inv, g_inv);

    cudaFuncSetAttribute(gemm_hmma, cudaFuncAttributeMaxDynamicSharedMemorySize, SMEMB);

    const long nd = (long)NN * DD;
    const long nu = (long)NN * UW;
    const long nn = (long)NN * NN;
    const long dd = (long)DD * DD;
    const long nY = (long)BB * NN * DD;

    // 1) operand prep:
    //    slot0 = 0.1*Wq^T, slot1 = Wo, slot2 = Wk^T, slot3 = Wv^T; y split
    {
        dim3 gt(DD / 32, DD / 32, 1);
        tsplit_k<<<gt, dim3(32, 8)>>>(Wq, Wh + 0 * dd, Wl + 0 * dd, DD, DD, 0.1f);
        splitf_k<<<(int)(dd / 1024), 256>>>(Wo, Wh + 1 * dd, Wl + 1 * dd, dd);
        tsplit_k<<<gt, dim3(32, 8)>>>(Wk, Wh + 2 * dd, Wl + 2 * dd, DD, DD, 1.0f);
        tsplit_k<<<gt, dim3(32, 8)>>>(Wv, Wh + 3 * dd, Wl + 3 * dd, DD, DD, 1.0f);
        splitf_k<<<(int)(nY / 1024), 256>>>(y, yh, yl, nY);
    }

    // 2) batched weight GEMMs (z=0: G = 0.1Wq^T @ Wk -> slot4,
    //                          z=1: W3 = Wo @ Wv     -> slot5)
    {
        dim3 g(DD / 128, DD / 128, 2);
        gemm_hmma<<<g, 256, SMEMB>>>(Wh + 0 * dd, Wl + 0 * dd,   // A: slot0 / slot1
                                     Wh + 2 * dd, Wl + 2 * dd,   // B: slot2 / slot3
                                     nullptr, Wh + 4 * dd, Wl + 4 * dd,  // C: slot4 / slot5
                                     DD, DD, DD, DD, dd, dd, dd, 1.0f, 1);
    }

    // 3) fused U|VW = y_flat @ [G; W3]^T  (Nc = 4096) -> bf16 split
    //    cols [0,2048) = U = y G^T ; cols [2048,4096) = VW = y W3^T = V Wo^T
    {
        dim3 g(UW / 128, (BB * NN) / 128, 1);
        gemm_hmma<<<g, 256, SMEMB>>>(yh, yl, Wh + 4 * dd, Wl + 4 * dd,
                                     nullptr, UVWh, UVWl,
                                     UW, DD, DD, DD, 0, 0, 0, 1.0f, 1);
    }

    // 4) logits per batch with fused exp: Aw[b] = exp(y[b] @ U[b]^T)
    //    U slice of UVW: row stride 4096, batch stride nu
    {
        dim3 g(NN / 128, NN / 128, BB);
        gemm_hmma<<<g, 256, SMEMB>>>(yh, yl, UVWh, UVWl, Aw, nullptr, nullptr,
                                     NN, DD, DD, UW, nd, nu, nn, 1.0f, 2);
    }

    // 5) VW transpose (bf16 hi/lo): VT[b][d][j] = UVW[b][j][2048+d]
    {
        dim3 g2(DD / 32, NN / 32, BB);
        tbf16_k<<<g2, dim3(32, 8)>>>(UVWh + DD, UVWl + DD, VTh, VTl,
                                     NN, DD, UW, nu, nd);
    }

    // 6) column sums (diag excluded) -> inv
    {
        dim3 g(NN / 256, BB, 1);
        colsum_k<<<g, 256>>>(Aw, inv);
    }

    // 7) fused normalize (writeback, diag=0) + transpose + bf16 split -> AT
    {
        dim3 g(NN / 32, NN / 32, BB);
        normtsplit_k<<<g, dim3(32, 8)>>>(Aw, inv, ATh, ATl);
    }

    // 8) out[b] = AT_b @ VT_b^T  (fp32 straight into d_out)
    {
        dim3 g(DD / 128, NN / 128, BB);
        gemm_hmma<<<g, 256, SMEMB>>>(ATh, ATl, VTh, VTl, out, nullptr, nullptr,
                                     DD, NN, NN, NN, nn, nd, nd, 1.0f, 0);
    }
}